// round 2
// baseline (speedup 1.0000x reference)
#include <cuda_runtime.h>
#include <math.h>

#define Bb 8
#define Cc 128
#define Nn 65536
#define Ll 64
#define SLICE 1024
#define SLICES 64          // Nn / SLICE
#define CHUNK 64
#define NCHUNK 16          // SLICE / CHUNK

// Scratch (no allocation allowed) — all fully overwritten every call.
__device__ float g_cen_part[Bb * SLICES * Ll * Cc];   // 16 MB per-slice center partials
__device__ float g_vpart[Bb * SLICES * Ll];
__device__ float g_cpart[Bb * SLICES * Ll];
__device__ float g_cen[Bb * Ll * Cc];                 // normalized centers
__device__ float g_sqn[Bb * Cc];                      // sum_l cen^2
__device__ float g_vc[Bb * Ll];                       // vsum/count per label

// ---------------------------------------------------------------------------
// MAIN: single DRAM pass. Block = (slice s, batch b), 128 threads.
// Per 64-point x 128-channel chunk:
//   load phase : gmem -> smem tile (coalesced) + register accum of s1/s2
//   scatter    : lane-owns-channel RMW into block-local cenacc[64][128]
// ---------------------------------------------------------------------------
__global__ __launch_bounds__(128) void kmain(const float* __restrict__ pred,
                                             const int* __restrict__ label,
                                             float* __restrict__ out, int out_size) {
    extern __shared__ float sm[];
    float* tile   = sm;                 // [128 ch][65]  (64 pts + 1 pad)
    float* cenacc = sm + 128 * 65;      // [64 lab][128 ch]
    float* ps1    = cenacc + Ll * Cc;   // [128]
    float* ps2    = ps1 + 128;          // [128]
    float* vbin   = ps2 + 128;          // [64]
    float* cbin   = vbin + 64;          // [64]
    int*   slab   = (int*)(cbin + 64);  // [64]

    const int t = threadIdx.x;          // 0..127
    const int s = blockIdx.x;           // slice
    const int b = blockIdx.y;

    if (s == 0 && b == 0)
        for (int i = t; i < out_size; i += 128) out[i] = 0.0f;

    for (int i = t; i < Ll * Cc; i += 128) cenacc[i] = 0.0f;
    if (t < Ll) { vbin[t] = 0.0f; cbin[t] = 0.0f; }
    __syncthreads();

    const int n0   = s * SLICE;
    const int pofs = t & 63;            // point within chunk
    const int cpar = t >> 6;            // channel parity (0/1)
    const float* base = pred + (size_t)b * Cc * Nn;

    for (int j = 0; j < NCHUNK; j++) {
        const int np = n0 + j * CHUNK;

        if (t < CHUNK) slab[t] = label[b * Nn + np + t];

        // ---- load + per-point stats (thread covers 64 channels of one point)
        float s1 = 0.0f, s2 = 0.0f;
        const float* p = base + (size_t)cpar * Nn + np + pofs;
        float* trow = tile + cpar * 65 + pofs;
#pragma unroll 16
        for (int c2 = 0; c2 < 64; c2++) {      // c = 2*c2 + cpar
            float x = p[(size_t)(2 * c2) * Nn];
            trow[c2 * 130] = x;                // (2*c2)*65
            s1 += x;
            s2 = fmaf(x, x, s2);
        }
        ps1[t] = s1; ps2[t] = s2;
        __syncthreads();

        // ---- var-loss finalize (one thread per point)
        if (t < CHUNK) {
            float S1 = ps1[t] + ps1[t + 64];
            float S2 = ps2[t] + ps2[t + 64];
            float pn2 = fmaxf(S2 - S1 * S1 * (1.0f / Cc), 0.0f);
            float d = sqrtf(pn2) - 0.5f;                  // D_VAR
            float v = (d > 0.0f) ? d * d : 0.0f;
            int lb = slab[t];
            atomicAdd(&vbin[lb], v);
            atomicAdd(&cbin[lb], 1.0f);
        }

        // ---- center scatter: thread t owns channel t (no collisions, no conflicts)
        {
            const float* tcol = tile + t * 65;
            float* ca = cenacc + t;            // cenacc[l*128 + t]
#pragma unroll 4
            for (int pp = 0; pp < CHUNK; pp++) {
                int lb = slab[pp];
                ca[lb * Cc] += tcol[pp];
            }
        }
        __syncthreads();
    }

    // ---- write per-slice partials (plain coalesced stores, no atomics)
    const size_t pb = ((size_t)b * SLICES + s) * (Ll * Cc);
    for (int i = t; i < Ll * Cc; i += 128) g_cen_part[pb + i] = cenacc[i];
    if (t < Ll) {
        g_vpart[(b * SLICES + s) * Ll + t] = vbin[t];
        g_cpart[(b * SLICES + s) * Ll + t] = cbin[t];
    }
}

// ---------------------------------------------------------------------------
// K2B: reduce slice partials -> normalized centers, sqn, var terms.
// Block (g, b): channels [g*16, g*16+16).
// ---------------------------------------------------------------------------
__global__ __launch_bounds__(128) void k2b() {
    const int g = blockIdx.x, b = blockIdx.y, t = threadIdx.x;
    __shared__ float scen[Ll][17];
    __shared__ float sinv[Ll];

    if (t < Ll) {
        float cs = 0.0f;
        for (int s = 0; s < SLICES; s++) cs += g_cpart[(b * SLICES + s) * Ll + t];
        sinv[t] = 1.0f / cs;
    }
    __syncthreads();

#pragma unroll
    for (int k = 0; k < 8; k++) {
        int idx = k * 128 + t;                 // 1024 outputs
        int l = idx >> 4, cp = idx & 15;
        int c = g * 16 + cp;
        float sum = 0.0f;
        for (int s = 0; s < SLICES; s++)
            sum += g_cen_part[((size_t)(b * SLICES + s)) * (Ll * Cc) + l * Cc + c];
        float cen = sum * sinv[l];
        g_cen[(b * Ll + l) * Cc + c] = cen;
        scen[l][cp] = cen;
    }
    __syncthreads();

    if (t < 16) {
        float q = 0.0f;
#pragma unroll 8
        for (int l = 0; l < Ll; l++) { float v = scen[l][t]; q = fmaf(v, v, q); }
        g_sqn[b * Cc + g * 16 + t] = q;
    }
    if (g == 0 && t < Ll) {
        float vs = 0.0f;
        for (int s = 0; s < SLICES; s++) vs += g_vpart[(b * SLICES + s) * Ll + t];
        g_vc[b * Ll + t] = vs * sinv[t];
    }
}

// ---------------------------------------------------------------------------
// K3: pairwise hinge + reg + var assembly. Block (q, b): d in [q*8, q*8+8).
// ---------------------------------------------------------------------------
__global__ __launch_bounds__(256) void k3(float* __restrict__ out) {
    const int q = blockIdx.x, b = blockIdx.y, t = threadIdx.x;
    __shared__ float cen[Ll][Cc];      // 32 KB
    __shared__ float sq[Cc];
    __shared__ float red[8];

    for (int i = t; i < Ll * Cc; i += 256) cen[i >> 7][i & 127] = g_cen[b * Ll * Cc + i];
    if (t < Cc) sq[t] = g_sqn[b * Cc + t];
    __syncthreads();

    float local = 0.0f;
#pragma unroll
    for (int k = 0; k < 4; k++) {
        int pr = k * 256 + t;                  // 1024 pairs per block
        int cc = pr & 127;
        int d  = q * 8 + (pr >> 7);
        float gg = 0.0f;
#pragma unroll 16
        for (int l = 0; l < Ll; l++) gg = fmaf(cen[l][cc], cen[l][d], gg);
        float sqd = fmaxf(sq[cc] + sq[d] - 2.0f * gg, 0.0f);
        float dist = (sqd > 0.0f) ? sqrtf(sqd) : 0.0f;
        float h = fmaxf(3.0f - dist, 0.0f);    // 2*D_DIST
        local = fmaf(h, h, local);
    }
    local *= (1.0f / 8064.0f);                 // P_DIST / (2*L*(L-1))

    if (q == 0) {
        if (t < Cc) local += 0.001f * sqrtf(sq[t]) * (1.0f / 64.0f);   // l_reg
        if (t < Ll) local += g_vc[b * Ll + t] * (1.0f / 64.0f);        // var
    }

    for (int off = 16; off > 0; off >>= 1)
        local += __shfl_down_sync(0xFFFFFFFFu, local, off);
    if ((t & 31) == 0) red[t >> 5] = local;
    __syncthreads();
    if (t == 0) {
        float ssum = 0.0f;
#pragma unroll
        for (int w = 0; w < 8; w++) ssum += red[w];
        atomicAdd(out, ssum);
    }
}

// ---------------------------------------------------------------------------
extern "C" void kernel_launch(void* const* d_in, const int* in_sizes, int n_in,
                              void* d_out, int out_size) {
    const float* pred  = (const float*)d_in[0];
    const int*   label = (const int*)d_in[1];
    float* out = (float*)d_out;

    const int smem_bytes = (128 * 65 + Ll * Cc + 128 + 128 + 64 + 64 + 64) * 4;
    cudaFuncSetAttribute(kmain, cudaFuncAttributeMaxDynamicSharedMemorySize, smem_bytes);

    kmain<<<dim3(SLICES, Bb), 128, smem_bytes>>>(pred, label, out, out_size);
    k2b<<<dim3(8, Bb), 128>>>();
    k3<<<dim3(16, Bb), 256>>>(out);
}

// round 3
// speedup vs baseline: 1.9633x; 1.9633x over previous
#include <cuda_runtime.h>
#include <math.h>

#define Bb 8
#define Cc 128
#define Nn 65536
#define Ll 64
#define SLABS 64                 // K1 slabs per batch, 1024 points each
#define NK1 (Bb * SLABS)         // 512 per-point blocks
#define NK2 (Bb * Cc)            // 1024 channel blocks

// Scratch in device globals (no allocation allowed). All fully overwritten
// every call (no atomically-accumulated global state -> no zeroing pass).
__device__ float g_censum[Bb * Ll * Cc];
__device__ float g_cen[Bb * Ll * Cc];
__device__ float g_sqn[Bb * Cc];
__device__ float g_vc[Bb * Ll];
__device__ float g_vpart[Bb * SLABS * Ll];
__device__ float g_cpart[Bb * SLABS * Ll];

// ---------------------------------------------------------------------------
// Merged single-grid kernel: two block types co-resident on the chip.
//   bid <  NK1 : per-point pass  (b, slab of 1024 points) -> var partials
//   bid >= NK1 : channel pass    (b, c) -> unnormalized center sums
// Dynamic smem = 66560 B (sized for the channel path; point path uses 512 B).
// ---------------------------------------------------------------------------
__global__ __launch_bounds__(256, 3) void kboth(const float* __restrict__ pred,
                                                const int* __restrict__ label) {
    extern __shared__ float sm[];
    const int t = threadIdx.x;
    const int bid = blockIdx.x;

    if (bid < NK1) {
        // ================= per-point pass =================
        const int b = bid >> 6, slab = bid & 63;
        const int n0 = slab * 1024;                      // 256 thr x 4 pts
        const float4* p4 = (const float4*)(pred + (size_t)b * Cc * Nn + n0);

        float s1x = 0.f, s1y = 0.f, s1z = 0.f, s1w = 0.f;
        float s2x = 0.f, s2y = 0.f, s2z = 0.f, s2w = 0.f;
#pragma unroll 8
        for (int c = 0; c < Cc; c++) {
            float4 v = p4[c * (Nn / 4) + t];
            s1x += v.x; s2x = fmaf(v.x, v.x, s2x);
            s1y += v.y; s2y = fmaf(v.y, v.y, s2y);
            s1z += v.z; s2z = fmaf(v.z, v.z, s2z);
            s1w += v.w; s2w = fmaf(v.w, v.w, s2w);
        }
        int4 lb = ((const int4*)(label + b * Nn + n0))[t];

        float* vbin = sm;            // [64]
        float* cbin = sm + 64;       // [64]
        if (t < Ll) { vbin[t] = 0.f; cbin[t] = 0.f; }
        __syncthreads();

        {
            float pn2, d, v;
            pn2 = fmaxf(s2x - s1x * s1x * (1.0f / Cc), 0.f);
            d = sqrtf(pn2) - 0.5f; v = (d > 0.f) ? d * d : 0.f;
            atomicAdd(&vbin[lb.x], v); atomicAdd(&cbin[lb.x], 1.f);
            pn2 = fmaxf(s2y - s1y * s1y * (1.0f / Cc), 0.f);
            d = sqrtf(pn2) - 0.5f; v = (d > 0.f) ? d * d : 0.f;
            atomicAdd(&vbin[lb.y], v); atomicAdd(&cbin[lb.y], 1.f);
            pn2 = fmaxf(s2z - s1z * s1z * (1.0f / Cc), 0.f);
            d = sqrtf(pn2) - 0.5f; v = (d > 0.f) ? d * d : 0.f;
            atomicAdd(&vbin[lb.z], v); atomicAdd(&cbin[lb.z], 1.f);
            pn2 = fmaxf(s2w - s1w * s1w * (1.0f / Cc), 0.f);
            d = sqrtf(pn2) - 0.5f; v = (d > 0.f) ? d * d : 0.f;
            atomicAdd(&vbin[lb.w], v); atomicAdd(&cbin[lb.w], 1.f);
        }
        __syncthreads();
        if (t < Ll) {
            g_vpart[(b * SLABS + slab) * Ll + t] = vbin[t];
            g_cpart[(b * SLABS + slab) * Ll + t] = cbin[t];
        }
    } else {
        // ================= channel pass =================
        const int id = bid - NK1;
        const int c = id & 127, b = id >> 7;
        float* acc = sm;             // [2 copies][64 labels][128 cols], stride 128
        float* red = sm + 16384;     // [256]

        for (int i = t; i < 16384; i += 256) acc[i] = 0.f;
        __syncthreads();

        const float4* p4 = (const float4*)(pred + (size_t)b * Cc * Nn + (size_t)c * Nn);
        const int4*   l4 = (const int4*)(label + b * Nn);
        const int copy_off = (t >> 7) * 8192;
        const int col = t & 127;
        float* ap = acc + copy_off + col;

#pragma unroll 2
        for (int i = 0; i < 64; i++) {           // 64 * 256 * float4 = 65536 pts
            int idx = i * 256 + t;
            float4 x = p4[idx];
            int4 L = l4[idx];
            ap[L.x * 128] += x.x;                // bank = col%32: conflict-free
            ap[L.y * 128] += x.y;
            ap[L.z * 128] += x.z;
            ap[L.w * 128] += x.w;
        }
        __syncthreads();

        // diagonal reduce (conflict-free despite stride 128)
        const int l = t & 63, q = t >> 6;
        float s = 0.f;
#pragma unroll 8
        for (int jj = 0; jj < 32; jj++) {
            int j = (q * 32 + jj + t) & 127;
            s += acc[l * 128 + j] + acc[8192 + l * 128 + j];
        }
        red[t] = s;
        __syncthreads();
        if (t < Ll)
            g_censum[((size_t)b * Ll + t) * Cc + c] =
                red[t] + red[t + 64] + red[t + 128] + red[t + 192];
    }
}

// ---------------------------------------------------------------------------
// kfinA: per-batch counts, normalized centers, sqn, var terms. Grid = B.
// Also zeroes d_out (runs before kfinB's atomics in stream order).
// ---------------------------------------------------------------------------
__global__ __launch_bounds__(256) void kfinA(float* __restrict__ out, int out_size) {
    const int b = blockIdx.x, t = threadIdx.x;
    __shared__ float scen[Ll][Cc];
    __shared__ float icnt[Ll];

    if (b == 0)
        for (int i = t; i < out_size; i += 256) out[i] = 0.f;

    if (t < Ll) {
        float cs = 0.f, vs = 0.f;
        for (int s = 0; s < SLABS; s++) {
            cs += g_cpart[(b * SLABS + s) * Ll + t];
            vs += g_vpart[(b * SLABS + s) * Ll + t];
        }
        icnt[t] = 1.0f / cs;
        g_vc[b * Ll + t] = vs / cs;
    }
    __syncthreads();

    for (int i = t; i < Ll * Cc; i += 256) {
        int l = i >> 7;
        float cv = g_censum[(size_t)b * Ll * Cc + i] * icnt[l];
        scen[l][i & 127] = cv;
        g_cen[(size_t)b * Ll * Cc + i] = cv;
    }
    __syncthreads();

    if (t < Cc) {
        float q = 0.f;
#pragma unroll 8
        for (int l = 0; l < Ll; l++) { float v = scen[l][t]; q = fmaf(v, v, q); }
        g_sqn[b * Cc + t] = q;
    }
}

// ---------------------------------------------------------------------------
// kfinB: pairwise hinge (register-tiled gram, 4 accumulators/thread) + reg/var
// assembly. Grid (16, B): block q covers d in [q*8, q*8+8).
// ---------------------------------------------------------------------------
__global__ __launch_bounds__(256) void kfinB(float* __restrict__ out) {
    const int q = blockIdx.x, b = blockIdx.y, t = threadIdx.x;
    __shared__ float cen[Ll][Cc];    // 32 KB
    __shared__ float sq[Cc];
    __shared__ float red[8];

    for (int i = t; i < Ll * Cc; i += 256)
        cen[i >> 7][i & 127] = g_cen[(size_t)b * Ll * Cc + i];
    if (t < Cc) sq[t] = g_sqn[b * Cc + t];
    __syncthreads();

    const int cc = t & 127;
    const int d0 = q * 8 + (t >> 7) * 4;
    float g0 = 0.f, g1 = 0.f, g2 = 0.f, g3 = 0.f;
#pragma unroll 8
    for (int l = 0; l < Ll; l++) {
        float a = cen[l][cc];
        g0 = fmaf(a, cen[l][d0 + 0], g0);
        g1 = fmaf(a, cen[l][d0 + 1], g1);
        g2 = fmaf(a, cen[l][d0 + 2], g2);
        g3 = fmaf(a, cen[l][d0 + 3], g3);
    }
    float gg[4] = {g0, g1, g2, g3};
    float local = 0.f;
#pragma unroll
    for (int j = 0; j < 4; j++) {
        float sqd = fmaxf(sq[cc] + sq[d0 + j] - 2.0f * gg[j], 0.f);
        float dist = (sqd > 0.f) ? sqrtf(sqd) : 0.f;
        float h = fmaxf(3.0f - dist, 0.f);       // 2*D_DIST
        local = fmaf(h, h, local);
    }
    local *= (1.0f / 8064.0f);                   // P_DIST / (2*L*(L-1))

    if (q == 0 && t < 128) {
        local += 0.001f * sqrtf(sq[t]) * (1.0f / 64.0f);      // l_reg
        if (t < Ll) local += g_vc[b * Ll + t] * (1.0f / 64.0f); // var
    }

    for (int off = 16; off > 0; off >>= 1)
        local += __shfl_down_sync(0xFFFFFFFFu, local, off);
    if ((t & 31) == 0) red[t >> 5] = local;
    __syncthreads();
    if (t == 0) {
        float s = 0.f;
#pragma unroll
        for (int w = 0; w < 8; w++) s += red[w];
        atomicAdd(out, s);
    }
}

// ---------------------------------------------------------------------------
extern "C" void kernel_launch(void* const* d_in, const int* in_sizes, int n_in,
                              void* d_out, int out_size) {
    const float* pred  = (const float*)d_in[0];
    const int*   label = (const int*)d_in[1];
    float* out = (float*)d_out;

    const int smem_bytes = (16384 + 256) * 4;    // 66560
    cudaFuncSetAttribute(kboth, cudaFuncAttributeMaxDynamicSharedMemorySize, smem_bytes);

    kboth<<<NK1 + NK2, 256, smem_bytes>>>(pred, label);
    kfinA<<<Bb, 256>>>(out, out_size);
    kfinB<<<dim3(16, Bb), 256>>>(out);
}

// round 4
// speedup vs baseline: 2.1494x; 1.0948x over previous
#include <cuda_runtime.h>
#include <math.h>

#define Bb 8
#define Cc 128
#define Nn 65536
#define Ll 64
#define SLABS 64                 // point-pass slabs per batch, 1024 points each
#define NK1 (Bb * SLABS)         // 512 point blocks
#define NK2 (Bb * Cc)            // 1024 channel blocks

// Scratch in device globals. All fully overwritten every call.
__device__ float g_censum[Bb * Ll * Cc];
__device__ float g_vpart[Bb * SLABS * Ll];
__device__ float g_cpart[Bb * SLABS * Ll];

// ---------------------------------------------------------------------------
// Merged single-grid kernel: two block types co-resident.
//   bid <  NK1 : per-point pass  (b, slab of 1024 points) -> var partials
//   bid >= NK1 : channel pass    (b, c) -> unnormalized center sums
// ---------------------------------------------------------------------------
__global__ __launch_bounds__(256, 3) void kboth(const float* __restrict__ pred,
                                                const int* __restrict__ label,
                                                float* __restrict__ out, int out_size) {
    extern __shared__ float sm[];
    const int t = threadIdx.x;
    const int bid = blockIdx.x;

    if (bid == 0)                       // zero output before kfin's atomics
        for (int i = t; i < out_size; i += 256) out[i] = 0.0f;

    if (bid < NK1) {
        // ================= per-point pass =================
        const int b = bid >> 6, slab = bid & 63;
        const int n0 = slab * 1024;                       // 256 thr x 4 pts
        const float4* p4 = (const float4*)(pred + (size_t)b * Cc * Nn + n0);

        float s1x = 0.f, s1y = 0.f, s1z = 0.f, s1w = 0.f;
        float s2x = 0.f, s2y = 0.f, s2z = 0.f, s2w = 0.f;
#pragma unroll 1
        for (int cs = 0; cs < 16; cs++) {                 // 16 stages x 8 channels
            float4 V[8];
#pragma unroll
            for (int k = 0; k < 8; k++)
                V[k] = p4[(size_t)(cs * 8 + k) * (Nn / 4) + t];
#pragma unroll
            for (int k = 0; k < 8; k++) {
                s1x += V[k].x; s2x = fmaf(V[k].x, V[k].x, s2x);
                s1y += V[k].y; s2y = fmaf(V[k].y, V[k].y, s2y);
                s1z += V[k].z; s2z = fmaf(V[k].z, V[k].z, s2z);
                s1w += V[k].w; s2w = fmaf(V[k].w, V[k].w, s2w);
            }
        }
        int4 lb = ((const int4*)(label + b * Nn + n0))[t];

        float* vbin = sm;            // [64]
        float* cbin = sm + 64;       // [64]
        if (t < Ll) { vbin[t] = 0.f; cbin[t] = 0.f; }
        __syncthreads();
        {
            float pn2, d, v;
            pn2 = fmaxf(s2x - s1x * s1x * (1.0f / Cc), 0.f);
            d = sqrtf(pn2) - 0.5f; v = (d > 0.f) ? d * d : 0.f;
            atomicAdd(&vbin[lb.x], v); atomicAdd(&cbin[lb.x], 1.f);
            pn2 = fmaxf(s2y - s1y * s1y * (1.0f / Cc), 0.f);
            d = sqrtf(pn2) - 0.5f; v = (d > 0.f) ? d * d : 0.f;
            atomicAdd(&vbin[lb.y], v); atomicAdd(&cbin[lb.y], 1.f);
            pn2 = fmaxf(s2z - s1z * s1z * (1.0f / Cc), 0.f);
            d = sqrtf(pn2) - 0.5f; v = (d > 0.f) ? d * d : 0.f;
            atomicAdd(&vbin[lb.z], v); atomicAdd(&cbin[lb.z], 1.f);
            pn2 = fmaxf(s2w - s1w * s1w * (1.0f / Cc), 0.f);
            d = sqrtf(pn2) - 0.5f; v = (d > 0.f) ? d * d : 0.f;
            atomicAdd(&vbin[lb.w], v); atomicAdd(&cbin[lb.w], 1.f);
        }
        __syncthreads();
        if (t < Ll) {
            g_vpart[(b * SLABS + slab) * Ll + t] = vbin[t];
            g_cpart[(b * SLABS + slab) * Ll + t] = cbin[t];
        }
    } else {
        // ================= channel pass =================
        const int id = bid - NK1;
        const int c = id & 127, b = id >> 7;
        float* acc = sm;             // [2 copies][64 labels][128 cols]
        float* red = sm + 16384;     // [256]

        for (int i = t; i < 16384; i += 256) acc[i] = 0.f;
        __syncthreads();

        const float4* p4 = (const float4*)(pred + (size_t)b * Cc * Nn + (size_t)c * Nn);
        const int4*   l4 = (const int4*)(label + b * Nn);
        float* ap = acc + (t >> 7) * 8192 + (t & 127);    // private column

#pragma unroll 1
        for (int s = 0; s < 16; s++) {                    // 16 stages x 4 float4
            float4 X[4]; int4 L[4];
#pragma unroll
            for (int k = 0; k < 4; k++) {
                int idx = (s * 4 + k) * 256 + t;
                X[k] = p4[idx];
                L[k] = l4[idx];
            }
#pragma unroll
            for (int k = 0; k < 4; k++) {
                ap[L[k].x * 128] += X[k].x;               // bank=col%32: conflict-free
                ap[L[k].y * 128] += X[k].y;
                ap[L[k].z * 128] += X[k].z;
                ap[L[k].w * 128] += X[k].w;
            }
        }
        __syncthreads();

        // diagonal reduce (conflict-free despite stride 128)
        const int l = t & 63, q = t >> 6;
        float s = 0.f;
#pragma unroll 8
        for (int jj = 0; jj < 32; jj++) {
            int j = (q * 32 + jj + t) & 127;
            s += acc[l * 128 + j] + acc[8192 + l * 128 + j];
        }
        red[t] = s;
        __syncthreads();
        if (t < Ll)
            g_censum[((size_t)b * Ll + t) * Cc + c] =
                red[t] + red[t + 64] + red[t + 128] + red[t + 192];
    }
}

// ---------------------------------------------------------------------------
// kfin: merged finalize. Grid (16, B). Each block re-derives counts and
// normalized centers from L2-resident partials (33 KB), computes its gram
// slice (d in [q*8, q*8+8)); q==0 adds reg + var terms.
// ---------------------------------------------------------------------------
__global__ __launch_bounds__(256) void kfin(float* __restrict__ out) {
    const int q = blockIdx.x, b = blockIdx.y, t = threadIdx.x;
    __shared__ float cen[Ll][Cc];    // 32 KB
    __shared__ float sq[Cc];
    __shared__ float icnt[Ll];
    __shared__ float red[8];

    if (t < Ll) {
        float cs = 0.f;
#pragma unroll 8
        for (int s = 0; s < SLABS; s++) cs += g_cpart[(b * SLABS + s) * Ll + t];
        icnt[t] = 1.0f / cs;
    }
    __syncthreads();

    for (int i = t; i < Ll * Cc; i += 256)
        cen[i >> 7][i & 127] = g_censum[(size_t)b * Ll * Cc + i] * icnt[i >> 7];
    __syncthreads();

    if (t < Cc) {
        float qq = 0.f;
#pragma unroll 8
        for (int l = 0; l < Ll; l++) { float v = cen[l][t]; qq = fmaf(v, v, qq); }
        sq[t] = qq;
    }
    __syncthreads();

    const int cc = t & 127;
    const int d0 = q * 8 + (t >> 7) * 4;
    float g0 = 0.f, g1 = 0.f, g2 = 0.f, g3 = 0.f;
#pragma unroll 8
    for (int l = 0; l < Ll; l++) {
        float a = cen[l][cc];
        g0 = fmaf(a, cen[l][d0 + 0], g0);
        g1 = fmaf(a, cen[l][d0 + 1], g1);
        g2 = fmaf(a, cen[l][d0 + 2], g2);
        g3 = fmaf(a, cen[l][d0 + 3], g3);
    }
    float gg[4] = {g0, g1, g2, g3};
    float local = 0.f;
#pragma unroll
    for (int j = 0; j < 4; j++) {
        float sqd = fmaxf(sq[cc] + sq[d0 + j] - 2.0f * gg[j], 0.f);
        float dist = (sqd > 0.f) ? sqrtf(sqd) : 0.f;
        float h = fmaxf(3.0f - dist, 0.f);       // 2*D_DIST
        local = fmaf(h, h, local);
    }
    local *= (1.0f / 8064.0f);                   // P_DIST / (2*L*(L-1))

    if (q == 0) {
        if (t < Cc) local += 0.001f * sqrtf(sq[t]) * (1.0f / 64.0f);   // l_reg
        if (t < Ll) {
            float vs = 0.f;
#pragma unroll 8
            for (int s = 0; s < SLABS; s++) vs += g_vpart[(b * SLABS + s) * Ll + t];
            local += vs * icnt[t] * (1.0f / 64.0f);                    // var
        }
    }

    for (int off = 16; off > 0; off >>= 1)
        local += __shfl_down_sync(0xFFFFFFFFu, local, off);
    if ((t & 31) == 0) red[t >> 5] = local;
    __syncthreads();
    if (t == 0) {
        float s = 0.f;
#pragma unroll
        for (int w = 0; w < 8; w++) s += red[w];
        atomicAdd(out, s);
    }
}

// ---------------------------------------------------------------------------
extern "C" void kernel_launch(void* const* d_in, const int* in_sizes, int n_in,
                              void* d_out, int out_size) {
    const float* pred  = (const float*)d_in[0];
    const int*   label = (const int*)d_in[1];
    float* out = (float*)d_out;

    const int smem_bytes = (16384 + 256) * 4;    // 66560
    cudaFuncSetAttribute(kboth, cudaFuncAttributeMaxDynamicSharedMemorySize, smem_bytes);

    kboth<<<NK1 + NK2, 256, smem_bytes>>>(pred, label, out, out_size);
    kfin<<<dim3(16, Bb), 256>>>(out);
}

// round 5
// speedup vs baseline: 2.2533x; 1.0483x over previous
#include <cuda_runtime.h>
#include <math.h>

#define Bb 8
#define Cc 128
#define Nn 65536
#define Ll 64
#define SLABS 64                 // point-pass slabs per batch, 1024 points each
#define NK1 (Bb * SLABS)         // 512 point blocks
#define NK2 (Bb * Cc)            // 1024 channel blocks

// Scratch in device globals. All fully overwritten every call.
__device__ float g_censum[Bb * Ll * Cc];
__device__ float g_vpart[Bb * SLABS * Ll];
__device__ float g_cpart[Bb * SLABS * Ll];

// ---------------------------------------------------------------------------
// Merged single-grid kernel, register double-buffered in both paths.
//   bid <  NK1 : per-point pass  (b, slab of 1024 points) -> var partials
//   bid >= NK1 : channel pass    (b, c) -> unnormalized center sums
// ---------------------------------------------------------------------------
__global__ __launch_bounds__(256, 3) void kboth(const float* __restrict__ pred,
                                                const int* __restrict__ label,
                                                float* __restrict__ out, int out_size) {
    extern __shared__ float sm[];
    const int t = threadIdx.x;
    const int bid = blockIdx.x;

    if (bid == 0)                       // zero output before kfin's atomics
        for (int i = t; i < out_size; i += 256) out[i] = 0.0f;

    if (bid < NK1) {
        // ================= per-point pass =================
        const int b = bid >> 6, slab = bid & 63;
        const int n0 = slab * 1024;                       // 256 thr x 4 pts
        const float4* p4 = (const float4*)(pred + (size_t)b * Cc * Nn + n0);

        float s1x = 0.f, s1y = 0.f, s1z = 0.f, s1w = 0.f;
        float s2x = 0.f, s2y = 0.f, s2z = 0.f, s2w = 0.f;
        float4 VA[8], VB[8];

#pragma unroll
        for (int k = 0; k < 8; k++) VA[k] = p4[(size_t)k * (Nn / 4) + t];

#pragma unroll 1
        for (int g = 0; g < 16; g += 2) {
#pragma unroll
            for (int k = 0; k < 8; k++)
                VB[k] = p4[(size_t)((g + 1) * 8 + k) * (Nn / 4) + t];
#pragma unroll
            for (int k = 0; k < 8; k++) {
                s1x += VA[k].x; s2x = fmaf(VA[k].x, VA[k].x, s2x);
                s1y += VA[k].y; s2y = fmaf(VA[k].y, VA[k].y, s2y);
                s1z += VA[k].z; s2z = fmaf(VA[k].z, VA[k].z, s2z);
                s1w += VA[k].w; s2w = fmaf(VA[k].w, VA[k].w, s2w);
            }
            if (g + 2 < 16) {
#pragma unroll
                for (int k = 0; k < 8; k++)
                    VA[k] = p4[(size_t)((g + 2) * 8 + k) * (Nn / 4) + t];
            }
#pragma unroll
            for (int k = 0; k < 8; k++) {
                s1x += VB[k].x; s2x = fmaf(VB[k].x, VB[k].x, s2x);
                s1y += VB[k].y; s2y = fmaf(VB[k].y, VB[k].y, s2y);
                s1z += VB[k].z; s2z = fmaf(VB[k].z, VB[k].z, s2z);
                s1w += VB[k].w; s2w = fmaf(VB[k].w, VB[k].w, s2w);
            }
        }
        int4 lb = ((const int4*)(label + b * Nn + n0))[t];

        float* vbin = sm;            // [64]
        float* cbin = sm + 64;       // [64]
        if (t < Ll) { vbin[t] = 0.f; cbin[t] = 0.f; }
        __syncthreads();
        {
            float pn2, d, v;
            pn2 = fmaxf(s2x - s1x * s1x * (1.0f / Cc), 0.f);
            d = sqrtf(pn2) - 0.5f; v = (d > 0.f) ? d * d : 0.f;
            atomicAdd(&vbin[lb.x], v); atomicAdd(&cbin[lb.x], 1.f);
            pn2 = fmaxf(s2y - s1y * s1y * (1.0f / Cc), 0.f);
            d = sqrtf(pn2) - 0.5f; v = (d > 0.f) ? d * d : 0.f;
            atomicAdd(&vbin[lb.y], v); atomicAdd(&cbin[lb.y], 1.f);
            pn2 = fmaxf(s2z - s1z * s1z * (1.0f / Cc), 0.f);
            d = sqrtf(pn2) - 0.5f; v = (d > 0.f) ? d * d : 0.f;
            atomicAdd(&vbin[lb.z], v); atomicAdd(&cbin[lb.z], 1.f);
            pn2 = fmaxf(s2w - s1w * s1w * (1.0f / Cc), 0.f);
            d = sqrtf(pn2) - 0.5f; v = (d > 0.f) ? d * d : 0.f;
            atomicAdd(&vbin[lb.w], v); atomicAdd(&cbin[lb.w], 1.f);
        }
        __syncthreads();
        if (t < Ll) {
            g_vpart[(b * SLABS + slab) * Ll + t] = vbin[t];
            g_cpart[(b * SLABS + slab) * Ll + t] = cbin[t];
        }
    } else {
        // ================= channel pass =================
        const int id = bid - NK1;
        const int c = id & 127, b = id >> 7;
        float* acc = sm;             // [2 copies][64 labels][128 cols]
        float* red = sm + 16384;     // [256]

        for (int i = t; i < 16384; i += 256) acc[i] = 0.f;
        __syncthreads();

        const float4* p4 = (const float4*)(pred + (size_t)b * Cc * Nn + (size_t)c * Nn);
        const int4*   l4 = (const int4*)(label + b * Nn);
        float* ap = acc + (t >> 7) * 8192 + (t & 127);    // private column

        float4 XA[4], XB[4]; int4 LA[4], LB[4];
#pragma unroll
        for (int k = 0; k < 4; k++) { XA[k] = p4[k * 256 + t]; LA[k] = l4[k * 256 + t]; }

#pragma unroll 1
        for (int s = 0; s < 16; s += 2) {
#pragma unroll
            for (int k = 0; k < 4; k++) {
                int idx = ((s + 1) * 4 + k) * 256 + t;
                XB[k] = p4[idx]; LB[k] = l4[idx];
            }
#pragma unroll
            for (int k = 0; k < 4; k++) {
                ap[LA[k].x * 128] += XA[k].x;             // bank=col%32: conflict-free
                ap[LA[k].y * 128] += XA[k].y;
                ap[LA[k].z * 128] += XA[k].z;
                ap[LA[k].w * 128] += XA[k].w;
            }
            if (s + 2 < 16) {
#pragma unroll
                for (int k = 0; k < 4; k++) {
                    int idx = ((s + 2) * 4 + k) * 256 + t;
                    XA[k] = p4[idx]; LA[k] = l4[idx];
                }
            }
#pragma unroll
            for (int k = 0; k < 4; k++) {
                ap[LB[k].x * 128] += XB[k].x;
                ap[LB[k].y * 128] += XB[k].y;
                ap[LB[k].z * 128] += XB[k].z;
                ap[LB[k].w * 128] += XB[k].w;
            }
        }
        __syncthreads();

        // diagonal reduce (conflict-free despite stride 128)
        const int l = t & 63, q = t >> 6;
        float s = 0.f;
#pragma unroll 8
        for (int jj = 0; jj < 32; jj++) {
            int j = (q * 32 + jj + t) & 127;
            s += acc[l * 128 + j] + acc[8192 + l * 128 + j];
        }
        red[t] = s;
        __syncthreads();
        if (t < Ll)
            g_censum[((size_t)b * Ll + t) * Cc + c] =
                red[t] + red[t + 64] + red[t + 128] + red[t + 192];
    }
}

// ---------------------------------------------------------------------------
// kfin: finalize, fully parallel reductions. Grid (8, B); block q covers
// d in [q*16, q*16+16). q==0 adds reg + var terms.
// ---------------------------------------------------------------------------
__global__ __launch_bounds__(256) void kfin(float* __restrict__ out) {
    const int q = blockIdx.x, b = blockIdx.y, t = threadIdx.x;
    __shared__ float cen[Ll][Cc];    // 32 KB
    __shared__ float ps[256];
    __shared__ float qs[256];
    __shared__ float sq[Cc];
    __shared__ float icnt[Ll];
    __shared__ float vsum[Ll];
    __shared__ float red[8];

    // ---- cooperative count + vpart reduction (16 loads per thread each)
    {
        const int l = t & 63, sg = t >> 6;            // 4 slab groups of 16
        float cs = 0.f, vv = 0.f;
#pragma unroll 4
        for (int k = 0; k < 16; k++) {
            int idx = (b * SLABS + sg * 16 + k) * Ll + l;
            cs += g_cpart[idx];
            vv += g_vpart[idx];
        }
        ps[t] = cs; qs[t] = vv;
    }
    __syncthreads();
    if (t < Ll) {
        float ctot = ps[t] + ps[t + 64] + ps[t + 128] + ps[t + 192];
        icnt[t] = 1.0f / ctot;
        vsum[t] = (qs[t] + qs[t + 64] + qs[t + 128] + qs[t + 192]) / ctot;
    }
    __syncthreads();

    // ---- normalized centers
    for (int i = t; i < Ll * Cc; i += 256)
        cen[i >> 7][i & 127] = g_censum[(size_t)b * Ll * Cc + i] * icnt[i >> 7];
    __syncthreads();

    // ---- sqn (parallel: 32 l per thread, combine)
    {
        const int c = t & 127, h = t >> 7;
        float s = 0.f;
#pragma unroll 8
        for (int l = h * 32; l < h * 32 + 32; l++) { float v = cen[l][c]; s = fmaf(v, v, s); }
        ps[t] = s;
    }
    __syncthreads();
    if (t < Cc) sq[t] = ps[t] + ps[t + 128];
    __syncthreads();

    // ---- gram slice: 8 accumulators, 1 lane-spread + 8 broadcast LDS per l
    const int cc = t & 127;
    const int d0 = q * 16 + (t >> 7) * 8;
    float g[8] = {0.f, 0.f, 0.f, 0.f, 0.f, 0.f, 0.f, 0.f};
#pragma unroll 8
    for (int l = 0; l < Ll; l++) {
        float a = cen[l][cc];
#pragma unroll
        for (int j = 0; j < 8; j++) g[j] = fmaf(a, cen[l][d0 + j], g[j]);
    }
    float local = 0.f;
#pragma unroll
    for (int j = 0; j < 8; j++) {
        float sqd = fmaxf(sq[cc] + sq[d0 + j] - 2.0f * g[j], 0.f);
        float dist = (sqd > 0.f) ? sqrtf(sqd) : 0.f;
        float h = fmaxf(3.0f - dist, 0.f);        // 2*D_DIST
        local = fmaf(h, h, local);
    }
    local *= (1.0f / 8064.0f);                    // P_DIST / (2*L*(L-1))

    if (q == 0) {
        if (t < Cc) local += 0.001f * sqrtf(sq[t]) * (1.0f / 64.0f);   // l_reg
        if (t < Ll) local += vsum[t] * (1.0f / 64.0f);                 // var
    }

    for (int off = 16; off > 0; off >>= 1)
        local += __shfl_down_sync(0xFFFFFFFFu, local, off);
    if ((t & 31) == 0) red[t >> 5] = local;
    __syncthreads();
    if (t == 0) {
        float s = 0.f;
#pragma unroll
        for (int w = 0; w < 8; w++) s += red[w];
        atomicAdd(out, s);
    }
}

// ---------------------------------------------------------------------------
extern "C" void kernel_launch(void* const* d_in, const int* in_sizes, int n_in,
                              void* d_out, int out_size) {
    const float* pred  = (const float*)d_in[0];
    const int*   label = (const int*)d_in[1];
    float* out = (float*)d_out;

    const int smem_bytes = (16384 + 256) * 4;     // 66560
    cudaFuncSetAttribute(kboth, cudaFuncAttributeMaxDynamicSharedMemorySize, smem_bytes);

    kboth<<<NK1 + NK2, 256, smem_bytes>>>(pred, label, out, out_size);
    kfin<<<dim3(8, Bb), 256>>>(out);
}